// round 12
// baseline (speedup 1.0000x reference)
#include <cuda_runtime.h>
#include <cuda_bf16.h>
#include <cstdint>
#include <cmath>

// Problem constants (fixed by setup_inputs):
//   x: (4, 16384, 512) fp32, w_qkv: (512,1536), b_qkv: (1536,)
//   w_proj: (512,512), b_proj: (512,), height=width=128, heads=8, hd=64
#define BATCH 4
#define SEQ   16384
#define CDIM  512
#define MTOT  (BATCH*SEQ)        // 65536
#define N1    1536
#define N2    512

// ---------------- scratch (device globals; no allocations allowed) ----------
__device__ float g_qkv[(long)MTOT * N1];     // post-rope/elu qkv (full fp32)
__device__ float g_attn[(long)MTOT * N2];    // attention output (tf32-rounded)
__device__ float g_xr[(long)MTOT * CDIM];    // x rounded to tf32 (RNA)
__device__ float g_kvp[2048 * 4096];         // per-chunk KV partials
__device__ float g_ksp[2048 * 64];           // per-chunk ksum partials
__device__ float g_kv[32 * 4096];            // reduced KV per (b,h)
__device__ float g_ksum[32 * 64];            // reduced ksum per (b,h)
__device__ float g_tab[4096];                // [0..2047]=cos, [2048..4095]=sin
__device__ float g_bt1[(long)N1 * CDIM];     // w_qkv^T, tf32-rounded
__device__ float g_bt2[(long)N2 * CDIM];     // w_proj^T, tf32-rounded

// ============================ PTX helpers ===================================
__device__ __forceinline__ uint32_t smem_to_u32(const void* p) {
    uint32_t a;
    asm("{ .reg .u64 t; cvta.to.shared.u64 t, %1; cvt.u32.u64 %0, t; }"
        : "=r"(a) : "l"(p));
    return a;
}

__device__ __forceinline__ void cp_async16(uint32_t saddr, const void* gaddr) {
    asm volatile("cp.async.cg.shared.global [%0], [%1], 16;\n"
                 :: "r"(saddr), "l"(gaddr) : "memory");
}

__device__ __forceinline__ void ldsm_x4(uint32_t* r, uint32_t addr) {
    asm volatile("ldmatrix.sync.aligned.m8n8.x4.shared.b16 {%0,%1,%2,%3}, [%4];"
                 : "=r"(r[0]), "=r"(r[1]), "=r"(r[2]), "=r"(r[3]) : "r"(addr));
}

__device__ __forceinline__ float tf32r(float v) {
    uint32_t o;
    asm("cvt.rna.tf32.f32 %0, %1;" : "=r"(o) : "f"(v));
    return __uint_as_float(o);
}

__device__ __forceinline__ void mma_tf32(float* c, const uint32_t* a,
                                         uint32_t b0, uint32_t b1) {
    asm volatile(
        "mma.sync.aligned.m16n8k8.row.col.f32.tf32.tf32.f32 "
        "{%0,%1,%2,%3}, {%4,%5,%6,%7}, {%8,%9}, {%0,%1,%2,%3};"
        : "+f"(c[0]), "+f"(c[1]), "+f"(c[2]), "+f"(c[3])
        : "r"(a[0]), "r"(a[1]), "r"(a[2]), "r"(a[3]), "r"(b0), "r"(b1));
}

// Packed fp32 (Blackwell FFMA2) helpers
__device__ __forceinline__ unsigned long long pack2(float v) {
    unsigned long long r;
    asm("mov.b64 %0, {%1, %1};" : "=l"(r) : "f"(v));
    return r;
}
__device__ __forceinline__ unsigned long long fma2(unsigned long long a,
                                                   unsigned long long b,
                                                   unsigned long long c) {
    unsigned long long d;
    asm("fma.rn.f32x2 %0, %1, %2, %3;" : "=l"(d) : "l"(a), "l"(b), "l"(c));
    return d;
}
__device__ __forceinline__ void lds_v2u64(unsigned long long* r, uint32_t addr) {
    asm volatile("ld.shared.v2.u64 {%0, %1}, [%2];"
                 : "=l"(r[0]), "=l"(r[1]) : "r"(addr));
}

// ============================ misc helpers ==================================
__device__ __forceinline__ float elu1(float u) {
    return u > 0.0f ? u + 1.0f : __expf(u);
}

__global__ void init_tables() {
    int id = blockIdx.x * blockDim.x + threadIdx.x;
    if (id < 2048) {
        int t = id >> 4;
        int i = id & 15;
        double freq = pow(10.0, -(double)i / 16.0);   // theta^(-4i/hd), theta=10
        double ang = (double)t * freq;
        g_tab[id]        = (float)cos(ang);
        g_tab[2048 + id] = (float)sin(ang);
    }
}

// round x to tf32 (RNA) once, so the GEMM mainloop needs no cvt
__global__ void round_x(const float* __restrict__ src, float* __restrict__ dst) {
    long i = ((long)blockIdx.x * 256 + threadIdx.x) * 4;
    if (i < (long)MTOT * CDIM) {
        float4 v = *(const float4*)(src + i);
        v.x = tf32r(v.x); v.y = tf32r(v.y);
        v.z = tf32r(v.z); v.w = tf32r(v.w);
        *(float4*)(dst + i) = v;
    }
}

// transpose src[R][Ccols] -> dst[Ccols][R], rounding to tf32 (RNA)
__global__ void transpose_k(const float* __restrict__ src, float* __restrict__ dst,
                            int R, int Ccols) {
    __shared__ float tile[32][33];
    int c0 = blockIdx.x * 32, r0 = blockIdx.y * 32;
    for (int i = threadIdx.y; i < 32; i += 8)
        tile[i][threadIdx.x] = src[(long)(r0 + i) * Ccols + c0 + threadIdx.x];
    __syncthreads();
    for (int i = threadIdx.y; i < 32; i += 8)
        dst[(long)(c0 + i) * R + r0 + threadIdx.x] = tf32r(tile[threadIdx.x][i]);
}

// ============ mma.sync TF32 GEMM: 128x128x32 tiles, 3-stage cp.async =========
#define BM 128
#define BN 128
#define BK 32
#define NCHUNK (CDIM / BK)       // 16
#define NSTAGE 3
#define TILE_BYTES 16384          // 128 rows x 128 B
#define STAGE_BYTES 32768         // A tile + B tile
#define SMEM_GEMM (NSTAGE * STAGE_BYTES)   // 98304

// swizzled byte offset for (row, 16B-seg)
__device__ __forceinline__ uint32_t swz(int row, int seg) {
    return (uint32_t)(row * 128 + ((seg ^ (row & 7)) << 4));
}

template<int NS, bool FUSED>
__global__ __launch_bounds__(256, 2)
void mma_gemm(const float* __restrict__ A, const float* __restrict__ Bt,
              const float* __restrict__ bias, float* __restrict__ C) {
    extern __shared__ __align__(1024) char smem[];
    const uint32_t sbase = smem_to_u32(smem);
    const int tid = threadIdx.x;
    const int wid = tid >> 5, lane = tid & 31;
    const int warp_m = wid >> 2;            // 0..1  -> 64 rows each
    const int warp_n = wid & 3;             // 0..3  -> 32 cols each
    const long mBase = (long)blockIdx.y * BM;
    const int  nBase = blockIdx.x * BN;

    // gmem load assignment: 16B seg (tid&7), row (tid>>3) + 32j
    const int segc = tid & 7;
    const int row0 = tid >> 3;
    const float* gA0 = A  + (mBase + row0) * CDIM + segc * 4;
    const float* gB0 = Bt + (long)(nBase + row0) * CDIM + segc * 4;

    float acc[4][4][4];
#pragma unroll
    for (int mt = 0; mt < 4; mt++)
#pragma unroll
        for (int nt = 0; nt < 4; nt++)
#pragma unroll
            for (int q = 0; q < 4; q++) acc[mt][nt][q] = 0.0f;

    // per-thread ldmatrix row constants
    const int arow0 = warp_m * 64 + (lane & 15);          // + mt*16
    const int a_l4  = lane >> 4;                          // seg low bit
    const int brow0 = warp_n * 32 + ((lane >> 4) << 3) + (lane & 7);  // + ntp*16
    const int b_l3  = (lane >> 3) & 1;

    auto compute_stage = [&](int s) {
        const uint32_t as = sbase + s * STAGE_BYTES;
        const uint32_t bs = as + TILE_BYTES;
#pragma unroll
        for (int kk = 0; kk < 4; kk++) {
            uint32_t af[4][4];
#pragma unroll
            for (int mt = 0; mt < 4; mt++) {
                const int r = arow0 + mt * 16;
                ldsm_x4(af[mt], as + swz(r, kk * 2 + a_l4));
            }
            uint32_t bf[2][4];
#pragma unroll
            for (int np = 0; np < 2; np++) {
                const int r = brow0 + np * 16;
                ldsm_x4(bf[np], bs + swz(r, kk * 2 + b_l3));
            }
            // inputs are pre-rounded tf32 -> no cvt needed in the hot loop
#pragma unroll
            for (int mt = 0; mt < 4; mt++)
#pragma unroll
                for (int nt = 0; nt < 4; nt++)
                    mma_tf32(acc[mt][nt], af[mt],
                             bf[nt >> 1][(nt & 1) * 2], bf[nt >> 1][(nt & 1) * 2 + 1]);
        }
    };

    auto load_chunk = [&](int kt) {
        const uint32_t ss = sbase + (kt % NSTAGE) * STAGE_BYTES;
        const float* ag = gA0 + kt * BK;
        const float* bg = gB0 + kt * BK;
#pragma unroll
        for (int j = 0; j < 4; j++) {
            const uint32_t off = swz(row0 + j * 32, segc);
            cp_async16(ss + off,              ag + (long)j * 32 * CDIM);
            cp_async16(ss + TILE_BYTES + off, bg + (long)j * 32 * CDIM);
        }
        asm volatile("cp.async.commit_group;\n" ::: "memory");
    };

    // ---------------- pipelined mainloop (one barrier per chunk) ----------------
    load_chunk(0);
    load_chunk(1);
    for (int kt = 0; kt < NCHUNK; kt++) {
        if (kt + 2 < NCHUNK) {
            asm volatile("cp.async.wait_group 1;\n" ::: "memory");
            __syncthreads();
            load_chunk(kt + 2);
        } else {
            asm volatile("cp.async.wait_group 0;\n" ::: "memory");
            __syncthreads();
        }
        compute_stage(kt % NSTAGE);
    }

    // ---------------- epilogue: bias [+ rope + elu] -> C ----------------
#pragma unroll
    for (int mt = 0; mt < 4; mt++) {
        const long r0g = mBase + warp_m * 64 + mt * 16 + (lane >> 2);
#pragma unroll
        for (int nt = 0; nt < 4; nt++) {
            const int col = nBase + warp_n * 32 + nt * 8 + 2 * (lane & 3);
            const float b0 = bias[col], b1 = bias[col + 1];
            bool plain = true;
            if (FUSED) plain = (col >= 1024);   // v part: no rope/elu
            if (plain) {
#pragma unroll
                for (int hh = 0; hh < 2; hh++) {
                    const long row = r0g + hh * 8;
                    float2 v;
                    v.x = acc[mt][nt][2 * hh]     + b0;
                    v.y = acc[mt][nt][2 * hh + 1] + b1;
                    *(float2*)&C[row * NS + col] = v;
                }
            } else {
                const int d0 = col & 63;
                const int half = (d0 >> 5) & 1;
                const int p = (d0 & 31) >> 1;
#pragma unroll
                for (int hh = 0; hh < 2; hh++) {
                    const long row = r0g + hh * 8;
                    const int n = (int)(row & (SEQ - 1));
                    const int t = half ? (n >> 7) : (n & 127);
                    const float cc = g_tab[t * 16 + p];
                    const float sn = g_tab[2048 + t * 16 + p];
                    const float xr = acc[mt][nt][2 * hh]     + b0;
                    const float xi = acc[mt][nt][2 * hh + 1] + b1;
                    float2 v;
                    v.x = elu1(xr * cc - xi * sn);
                    v.y = elu1(xr * sn + xi * cc);
                    *(float2*)&C[row * NS + col] = v;
                }
            }
        }
    }
}

// ---------------- KV / ksum partial reduction ----------------
__global__ __launch_bounds__(256)
void kv_partial() {
    const int chunk = blockIdx.x;
    const int bh = blockIdx.y;
    const int b = bh >> 3, h = bh & 7;
    const int tid = threadIdx.x;
    const int d  = tid & 63;
    const int e0 = (tid >> 6) << 4;
    const int lr = tid >> 6;
    const int ld = tid & 63;

    __shared__ __align__(16) float ks[4][64];
    __shared__ __align__(16) float vs[4][64];
    const uint32_t vsb = smem_to_u32(vs);

    unsigned long long acc2[8];
#pragma unroll
    for (int e = 0; e < 8; e++) acc2[e] = 0ull;
    float ksacc = 0.0f;

    const long base = (long)(b * SEQ + chunk * 256) * N1 + h * 64;
    const float* Kp = g_qkv + base + 512;
    const float* Vp = g_qkv + base + 1024;

    for (int g = 0; g < 256; g += 4) {
        ks[lr][ld] = Kp[(long)(g + lr) * N1 + ld];
        vs[lr][ld] = Vp[(long)(g + lr) * N1 + ld];
        __syncthreads();
#pragma unroll
        for (int r = 0; r < 4; r++) {
            float kd = ks[r][d];
            if (tid < 64) ksacc += kd;
            unsigned long long kd2 = pack2(kd);
            const uint32_t a = vsb + (uint32_t)((r * 64 + e0) * 4);
            unsigned long long vr[8];
#pragma unroll
            for (int i = 0; i < 4; i++) lds_v2u64(&vr[i * 2], a + i * 16);
#pragma unroll
            for (int i = 0; i < 8; i++) acc2[i] = fma2(kd2, vr[i], acc2[i]);
        }
        __syncthreads();
    }

    float* out = g_kvp + ((long)(bh * 64 + chunk)) * 4096 + d * 64 + e0;
#pragma unroll
    for (int i = 0; i < 8; i += 2) {
        float2 f0 = *(float2*)&acc2[i];
        float2 f1 = *(float2*)&acc2[i + 1];
        float4 v4 = make_float4(f0.x, f0.y, f1.x, f1.y);
        *(float4*)&out[i * 2] = v4;
    }
    if (tid < 64) g_ksp[(bh * 64 + chunk) * 64 + tid] = ksacc;
}

__global__ void kv_reduce() {
    int gid = blockIdx.x * 256 + threadIdx.x;
    if (gid < 32 * 4096) {
        int bh = gid >> 12;
        int rem = gid & 4095;
        const float* p = g_kvp + (long)bh * 64 * 4096 + rem;
        float s = 0.0f;
#pragma unroll 8
        for (int c = 0; c < 64; c++) s += p[(long)c * 4096];
        g_kv[gid] = s;
    } else {
        int idx = gid - 32 * 4096;
        if (idx < 2048) {
            int bh = idx >> 6, dd = idx & 63;
            const float* p = g_ksp + bh * 64 * 64 + dd;
            float s = 0.0f;
#pragma unroll 8
            for (int c = 0; c < 64; c++) s += p[c * 64];
            g_ksum[idx] = s;
        }
    }
}

// ---------------- apply: out = tf32r((q @ KV) * 1/(q.ksum + 1e-6)) ----------
__global__ __launch_bounds__(256)
void apply_kernel() {
    const int chunk = blockIdx.x;
    const int bh = blockIdx.y;
    const int b = bh >> 3, h = bh & 7;
    const int tid = threadIdx.x;

    __shared__ __align__(16) float kv_sh[4096];
    __shared__ float ks_sh[64];
    const uint32_t kvb = smem_to_u32(kv_sh);
    for (int i = tid; i < 4096; i += 256) kv_sh[i] = g_kv[bh * 4096 + i];
    if (tid < 64) ks_sh[tid] = g_ksum[bh * 64 + tid];
    __syncthreads();

    const int n = chunk * 256 + tid;
    const float* qp = g_qkv + (long)(b * SEQ + n) * N1 + h * 64;
    float q[64];
#pragma unroll
    for (int i = 0; i < 16; i++)
        *(float4*)&q[i * 4] = *(const float4*)&qp[i * 4];

    float denom = 0.0f;
#pragma unroll
    for (int d = 0; d < 64; d++) denom += q[d] * ks_sh[d];
    float z = 1.0f / (denom + 1e-6f);

    float* op = g_attn + (long)(b * SEQ + n) * N2 + h * 64;
#pragma unroll
    for (int eh = 0; eh < 64; eh += 32) {
        unsigned long long o2[16];
#pragma unroll
        for (int i = 0; i < 16; i++) o2[i] = 0ull;
#pragma unroll 8
        for (int d = 0; d < 64; d++) {
            unsigned long long qd2 = pack2(q[d]);
            const uint32_t a = kvb + (uint32_t)((d * 64 + eh) * 4);
            unsigned long long vr[16];
#pragma unroll
            for (int i = 0; i < 8; i++) lds_v2u64(&vr[i * 2], a + i * 16);
#pragma unroll
            for (int i = 0; i < 16; i++) o2[i] = fma2(qd2, vr[i], o2[i]);
        }
#pragma unroll
        for (int i = 0; i < 16; i += 2) {
            float2 f0 = *(float2*)&o2[i];
            float2 f1 = *(float2*)&o2[i + 1];
            // round to tf32 here so the proj GEMM needs no cvt (numerics identical)
            float4 v4;
            v4.x = tf32r(f0.x * z); v4.y = tf32r(f0.y * z);
            v4.z = tf32r(f1.x * z); v4.w = tf32r(f1.y * z);
            *(float4*)&op[eh + i * 2] = v4;
        }
    }
}

// ---------------- launch ----------------
extern "C" void kernel_launch(void* const* d_in, const int* in_sizes, int n_in,
                              void* d_out, int out_size) {
    (void)in_sizes; (void)n_in; (void)out_size;
    const float* x      = (const float*)d_in[0];
    const float* w_qkv  = (const float*)d_in[1];
    const float* b_qkv  = (const float*)d_in[2];
    const float* w_proj = (const float*)d_in[3];
    const float* b_proj = (const float*)d_in[4];
    float* out = (float*)d_out;

    float *p_qkv = nullptr, *p_attn = nullptr, *p_xr = nullptr;
    float *p_bt1 = nullptr, *p_bt2 = nullptr;
    cudaGetSymbolAddress((void**)&p_qkv,  g_qkv);
    cudaGetSymbolAddress((void**)&p_attn, g_attn);
    cudaGetSymbolAddress((void**)&p_xr,   g_xr);
    cudaGetSymbolAddress((void**)&p_bt1,  g_bt1);
    cudaGetSymbolAddress((void**)&p_bt2,  g_bt2);

    cudaFuncSetAttribute((const void*)mma_gemm<N1, true>,
                         cudaFuncAttributeMaxDynamicSharedMemorySize, SMEM_GEMM);
    cudaFuncSetAttribute((const void*)mma_gemm<N2, false>,
                         cudaFuncAttributeMaxDynamicSharedMemorySize, SMEM_GEMM);

    init_tables<<<8, 256>>>();
    transpose_k<<<dim3(N1 / 32, CDIM / 32), dim3(32, 8)>>>(w_qkv,  p_bt1, CDIM, N1);
    transpose_k<<<dim3(N2 / 32, CDIM / 32), dim3(32, 8)>>>(w_proj, p_bt2, CDIM, N2);
    round_x<<<(MTOT * (long)CDIM / 4 + 255) / 256, 256>>>(x, p_xr);

    // QKV GEMM (tf32 mma.sync, pre-rounded operands) + bias + rope + elu+1 fused
    mma_gemm<N1, true><<<dim3(N1 / BN, MTOT / BM), 256, SMEM_GEMM>>>(
        p_xr, p_bt1, b_qkv, p_qkv);

    // KV / ksum reduction (two-phase, deterministic)
    kv_partial<<<dim3(64, 32), 256>>>();
    kv_reduce<<<520, 256>>>();

    // apply attention (writes tf32-rounded attn)
    apply_kernel<<<dim3(64, 32), 256>>>();

    // projection GEMM (tf32 mma.sync, pre-rounded operands) + bias
    mma_gemm<N2, false><<<dim3(N2 / BN, MTOT / BM), 256, SMEM_GEMM>>>(
        p_attn, p_bt2, b_proj, out);
}